// round 6
// baseline (speedup 1.0000x reference)
#include <cuda_runtime.h>
#include <cuda_bf16.h>

#define Gg 64
#define Nn 2048
#define Ee 16384
#define Ff 128
#define GE (Gg*Ee)          // 1048576 edges total
#define NL (Nn-1)           // 2047 non-center nodes per graph

// ---------------- scratch (static __device__ — no allocs allowed) ----------
__device__ int   g_is64;
__device__ int   g_deg[Gg*Nn];            // in-degree per global node
__device__ int   g_ccnt[Gg];              // # edges into center per graph
__device__ int   g_clist[Gg*128];         // edge ids into center (cap 128)
__device__ float g_A[Gg*Ff];              // ce@Wm_top + bm per graph
__device__ int   g_cnt[Nn];               // per-dst_local edge counts
__device__ int   g_off[Nn+1];             // CSR offsets
__device__ int   g_cur[Nn];               // scatter cursors
__device__ int   g_esrc[GE];              // CSR payload: src global id
__device__ float g_ecoef[GE];             // CSR payload: dis[src]*dis[dst]
__device__ float g_y[(size_t)Gg*Nn*Ff];   // mask*x  (67 MB)
__device__ float g_Zc[NL*Ff];             // mean_g aggregated y
__device__ float g_Zx[NL*Ff];             // mean_g aggregated x

__device__ __forceinline__ int ld_idx(const void* p, int is64, long long i) {
    return is64 ? (int)((const long long*)p)[i] : ((const int*)p)[i];
}

// ---------------- int32/int64 detection ------------------------------------
__global__ void k_detect(const unsigned int* w) {
    __shared__ int any;
    if (threadIdx.x == 0) any = 0;
    __syncthreads();
    int loc = 0;
    for (int i = threadIdx.x; i < 4096; i += blockDim.x) loc |= w[2*i + 1];
    if (loc) atomicOr(&any, 1);
    __syncthreads();
    if (threadIdx.x == 0) g_is64 = (any == 0) ? 1 : 0;
}

// ---------------- in-degree ------------------------------------------------
__global__ void k_deg(const void* ei) {
    int is64 = g_is64;
    int i = blockIdx.x * blockDim.x + threadIdx.x;
    if (i < GE) {
        int d = ld_idx(ei, is64, (long long)GE + i);
        atomicAdd(&g_deg[d], 1);
    }
}

// ---------------- find edges into the center node --------------------------
__global__ void k_centerfind(const void* ei, const void* centers) {
    int is64 = g_is64;
    int i = blockIdx.x * blockDim.x + threadIdx.x;
    if (i >= GE) return;
    int d = ld_idx(ei, is64, (long long)GE + i);
    int g = d / Nn;
    int c = ld_idx(centers, is64, g);
    if (d - g * Nn == c) {
        int p = atomicAdd(&g_ccnt[g], 1);
        if (p < 128) g_clist[g*128 + p] = i;
    }
}

// ---------------- ce = h1[center],  A = ce@Wm_top + bm ----------------------
__global__ void k_ceA(const void* ei, const void* centers,
                      const float* __restrict__ x,
                      const float* __restrict__ W1, const float* __restrict__ b1,
                      const float* __restrict__ Wm, const float* __restrict__ bm) {
    int g = blockIdx.x, t = threadIdx.x;
    int is64 = g_is64;
    __shared__ int list[128];
    __shared__ int nsh;
    __shared__ float cex[Ff], ce[Ff];
    if (t == 0) nsh = min(g_ccnt[g], 128);
    __syncthreads();
    int n = nsh;
    if (t < n) list[t] = g_clist[g*128 + t];
    __syncthreads();
    if (t == 0) {  // sort by edge id -> deterministic accumulation order
        for (int a = 1; a < n; a++) {
            int v = list[a]; int b = a - 1;
            while (b >= 0 && list[b] > v) { list[b+1] = list[b]; b--; }
            list[b+1] = v;
        }
    }
    __syncthreads();
    int cidx = ld_idx(centers, is64, g);
    int cg = g * Nn + cidx;
    float degc = (float)(1 + g_deg[cg]);
    float disC = rsqrtf(degc);
    float acc = 0.f;
    for (int k = 0; k < n; k++) {
        int e = list[k];
        int s = ld_idx(ei, is64, (long long)e);
        float coef = rsqrtf((float)(1 + g_deg[s])) * disC;
        acc += x[(size_t)s*Ff + t] * coef;
    }
    acc += x[(size_t)cg*Ff + t] / degc;          // self term
    cex[t] = acc;
    __syncthreads();
    float a1 = b1[t];
    for (int f = 0; f < Ff; f++) a1 += cex[f] * W1[f*Ff + t];
    ce[t] = a1;
    __syncthreads();
    float a2 = bm[t];
    for (int h = 0; h < Ff; h++) a2 += ce[h] * Wm[h*Ff + t];   // Wm top rows
    g_A[g*Ff + t] = a2;
}

// ---------------- mask & y = mask*x (big GEMM, 131008x128x128) --------------
// 256 threads: two col-groups of 128, each handles 16 rows of a 32-row tile.
__global__ void k_masky(const float* __restrict__ x, const float* __restrict__ Wb) {
    extern __shared__ float sm[];
    float* Ws = sm;              // 128x128
    float* Xs = sm + 16384;      // 32x128
    float4* Ws4 = (float4*)Ws;
    float4* Xs4 = (float4*)Xs;
    int t = threadIdx.x;

    const float4* Wb4 = (const float4*)Wb;
    for (int i = t; i < 4096; i += 256) Ws4[i] = Wb4[i];
    __syncthreads();

    const int NT = (Gg * NL) / 32;   // 4094 tiles
    for (int tile = blockIdx.x; tile < NT; tile += gridDim.x) {
        int r0 = tile * 32;
        for (int k = t; k < 32*32; k += 256) {
            int r = k >> 5, f4 = k & 31;
            int rg = r0 + r;
            int g = rg / NL, v = rg - g * NL;
            int grow = g * Nn + v;
            Xs4[r*32 + f4] = ((const float4*)x)[(size_t)grow*32 + f4];
        }
        __syncthreads();
        int p = t >> 7, col = t & 127;
        float acc[16];
        #pragma unroll
        for (int r = 0; r < 16; r++) acc[r] = 0.f;
        #pragma unroll 4
        for (int f4 = 0; f4 < 32; f4++) {
            float w0 = Ws[(4*f4 + 0)*128 + col];
            float w1 = Ws[(4*f4 + 1)*128 + col];
            float w2 = Ws[(4*f4 + 2)*128 + col];
            float w3 = Ws[(4*f4 + 3)*128 + col];
            #pragma unroll
            for (int r = 0; r < 16; r++) {
                float4 xv = Xs4[(p*16 + r)*32 + f4];
                acc[r] += xv.x*w0 + xv.y*w1 + xv.z*w2 + xv.w*w3;
            }
        }
        #pragma unroll
        for (int r = 0; r < 16; r++) {
            int rg = r0 + p*16 + r;
            int g = rg / NL, v = rg - g * NL;
            int grow = g * Nn + v;
            float m = fmaxf(g_A[g*128 + col] + acc[r], 0.f);
            g_y[(size_t)grow*128 + col] = m * Xs[(p*16 + r)*128 + col];
        }
        __syncthreads();
    }
}

// ---------------- CSR build: count / scan / scatter -------------------------
__global__ void k_cnt(const void* ei) {
    __shared__ int h[Nn];
    for (int i = threadIdx.x; i < Nn; i += blockDim.x) h[i] = 0;
    __syncthreads();
    int is64 = g_is64;
    for (int i = blockIdx.x * blockDim.x + threadIdx.x; i < GE;
         i += gridDim.x * blockDim.x) {
        int d = ld_idx(ei, is64, (long long)GE + i);
        atomicAdd(&h[d & (Nn - 1)], 1);     // d % 2048
    }
    __syncthreads();
    for (int i = threadIdx.x; i < Nn; i += blockDim.x)
        if (h[i]) atomicAdd(&g_cnt[i], h[i]);
}

__global__ void k_scan() {
    __shared__ int a[Nn], b[Nn];
    int t = threadIdx.x;
    a[t] = g_cnt[t]; a[t + 1024] = g_cnt[t + 1024];
    __syncthreads();
    int* src = a; int* dst = b;
    for (int off = 1; off < Nn; off <<= 1) {
        for (int i = t; i < Nn; i += 1024) {
            int v = src[i];
            if (i >= off) v += src[i - off];
            dst[i] = v;
        }
        __syncthreads();
        int* tmp = src; src = dst; dst = tmp;
    }
    for (int i = t; i < Nn; i += 1024) {
        int excl = i ? src[i-1] : 0;
        g_off[i] = excl;
        g_cur[i] = excl;
    }
    if (t == 0) g_off[Nn] = src[Nn-1];
}

__global__ void k_scatter(const void* ei) {
    int is64 = g_is64;
    int i = blockIdx.x * blockDim.x + threadIdx.x;
    if (i >= GE) return;
    int s = ld_idx(ei, is64, (long long)i);
    int d = ld_idx(ei, is64, (long long)GE + i);
    int dl = d & (Nn - 1);
    int pos = atomicAdd(&g_cur[dl], 1);
    g_esrc[pos] = s;
    g_ecoef[pos] = rsqrtf((float)(1 + g_deg[s])) * rsqrtf((float)(1 + g_deg[d]));
}

// ---------------- pull aggregation: Zc, Zx ----------------------------------
__global__ void k_pull(const float* __restrict__ x) {
    int d = blockIdx.x, t = threadIdx.x;
    __shared__ int   ss[128];
    __shared__ float sc[128];
    float ac = 0.f, ax = 0.f;
    int beg = g_off[d], end = g_off[d+1];
    for (int j0 = beg; j0 < end; j0 += 128) {
        int n = min(128, end - j0);
        if (t < n) { ss[t] = g_esrc[j0 + t]; sc[t] = g_ecoef[j0 + t]; }
        __syncthreads();
        #pragma unroll 4
        for (int j = 0; j < n; j++) {
            int s = ss[j]; float c = sc[j];
            size_t base = (size_t)s*Ff + t;
            ac += g_y[base] * c;
            ax += __ldg(&x[base]) * c;
        }
        __syncthreads();
    }
    #pragma unroll 4
    for (int g = 0; g < Gg; g++) {           // self terms, all graphs
        int row = g * Nn + d;
        float invd = 1.0f / (float)(1 + g_deg[row]);
        size_t base = (size_t)row*Ff + t;
        ac += g_y[base] * invd;
        ax += __ldg(&x[base]) * invd;
    }
    const float inv = 1.0f / (float)Gg;
    g_Zc[d*Ff + t] = ac * inv;
    g_Zx[d*Ff + t] = ax * inv;
}

// ---------------- output GEMMs: core = Zc@W2+b2, red = (Zx-Zc)@W3+b3 --------
__global__ void k_out(const float* __restrict__ W2, const float* __restrict__ b2,
                      const float* __restrict__ W3, const float* __restrict__ b3,
                      float* __restrict__ out) {
    int t = threadIdx.x;
    int d0 = blockIdx.x * 16;
    int nr = min(16, NL - d0);
    __shared__ float zc[16][128], zr[16][128];
    for (int r = 0; r < nr; r++) {
        float c = g_Zc[(d0 + r)*128 + t];
        zc[r][t] = c;
        zr[r][t] = g_Zx[(d0 + r)*128 + t] - c;
    }
    __syncthreads();
    float a[16], b[16];
    #pragma unroll
    for (int r = 0; r < 16; r++) { a[r] = b2[t]; b[r] = b3[t]; }
    for (int k = 0; k < 128; k++) {
        float w2 = W2[k*128 + t], w3 = W3[k*128 + t];
        #pragma unroll
        for (int r = 0; r < 16; r++) {
            a[r] += zc[r][k] * w2;
            b[r] += zr[r][k] * w3;
        }
    }
    for (int r = 0; r < nr; r++) {
        out[(size_t)(d0 + r)*128 + t] = a[r];
        out[(size_t)NL*128 + (size_t)(d0 + r)*128 + t] = b[r];
    }
}

// ---------------- launch -----------------------------------------------------
extern "C" void kernel_launch(void* const* d_in, const int* in_sizes, int n_in,
                              void* d_out, int out_size) {
    const float* x       = (const float*)d_in[0];
    const void*  ei      = d_in[1];
    const void*  centers = d_in[3];
    const float* W1 = (const float*)d_in[4];
    const float* b1 = (const float*)d_in[5];
    const float* W2 = (const float*)d_in[6];
    const float* b2 = (const float*)d_in[7];
    const float* W3 = (const float*)d_in[8];
    const float* b3 = (const float*)d_in[9];
    const float* Wm = (const float*)d_in[10];
    const float* bm = (const float*)d_in[11];
    float* out = (float*)d_out;

    void *p_deg, *p_ccnt, *p_cnt;
    cudaGetSymbolAddress(&p_deg,  g_deg);
    cudaGetSymbolAddress(&p_ccnt, g_ccnt);
    cudaGetSymbolAddress(&p_cnt,  g_cnt);
    cudaMemsetAsync(p_deg,  0, sizeof(int)*Gg*Nn);
    cudaMemsetAsync(p_ccnt, 0, sizeof(int)*Gg);
    cudaMemsetAsync(p_cnt,  0, sizeof(int)*Nn);

    k_detect<<<1, 256>>>((const unsigned int*)ei);
    k_deg<<<GE/256, 256>>>(ei);
    k_centerfind<<<GE/256, 256>>>(ei, centers);
    k_ceA<<<Gg, 128>>>(ei, centers, x, W1, b1, Wm, bm);

    int smem = (16384 + 32*128) * 4;   // 80 KB
    cudaFuncSetAttribute(k_masky, cudaFuncAttributeMaxDynamicSharedMemorySize, smem);
    k_masky<<<592, 256, smem>>>(x, Wm + Ff*Ff);   // bottom half of Wm

    k_cnt<<<512, 256>>>(ei);
    k_scan<<<1, 1024>>>();
    k_scatter<<<GE/256, 256>>>(ei);
    k_pull<<<NL, 128>>>(x);
    k_out<<<(NL + 15)/16, 128>>>(W2, b2, W3, b3, out);
}